// round 1
// baseline (speedup 1.0000x reference)
#include <cuda_runtime.h>
#include <math.h>

#define BSZ 4096
#define HSZ 512
#define KSZ 32
#define DSZ 20
#define NPAIR 496   // 32*31/2

// ---------------- device scratch (no allocations allowed) ----------------
__device__ float g_pm[32][KSZ][HSZ];   // per-b-block partial class sums  (2 MB)
__device__ float g_ps[32][KSZ][HSZ];   // per-b-block partial sum h^2 c^2 (2 MB)
__device__ float g_m[KSZ][HSZ];        // class_sums^T  [k][h]
__device__ float g_w[KSZ][HSZ];        // within^T      [k][h]
__device__ float g_counts[KSZ];
__device__ double g_pair[NPAIR];

// ---------------- stage 1: two fused tall-skinny matmuls ----------------
// grid (32 b-blocks, 4 h-blocks), 256 threads. Block tile: 128h x 32k x 128b.
// Thread tile 4h x 4k -> 32 FMA per 12 LDS floats.
__global__ __launch_bounds__(256) void stats_kernel(const float* __restrict__ hidden,
                                                    const float* __restrict__ cluster) {
    const int bb = blockIdx.x;       // 0..31
    const int hb = blockIdx.y;       // 0..3
    const int h0 = hb * 128;
    const int b0 = bb * 128;
    const int tid = (int)threadIdx.x;
    const int hg = tid >> 3;         // 0..31 (owns 4 h)
    const int kg = tid & 7;          // 0..7  (owns 4 k)

    __shared__ float sh_hid[32][128];
    __shared__ float sh_c[32][KSZ];
    __shared__ float sh_c2[32][KSZ];

    float am[4][4], as[4][4];
#pragma unroll
    for (int i = 0; i < 4; i++)
#pragma unroll
        for (int j = 0; j < 4; j++) { am[i][j] = 0.f; as[i][j] = 0.f; }

    for (int bt = 0; bt < 128; bt += 32) {
        __syncthreads();
#pragma unroll
        for (int i = tid; i < 32 * 128; i += 256) {
            int r = i >> 7, c = i & 127;
            sh_hid[r][c] = hidden[(b0 + bt + r) * HSZ + h0 + c];
        }
#pragma unroll
        for (int i = tid; i < 32 * 32; i += 256) {
            int r = i >> 5, c = i & 31;
            float v = cluster[(b0 + bt + r) * KSZ + c];
            sh_c[r][c] = v;
            sh_c2[r][c] = v * v;
        }
        __syncthreads();
#pragma unroll 4
        for (int r = 0; r < 32; r++) {
            float hv[4], h2[4], cv[4], c2v[4];
#pragma unroll
            for (int i = 0; i < 4; i++) { hv[i] = sh_hid[r][hg * 4 + i]; h2[i] = hv[i] * hv[i]; }
#pragma unroll
            for (int j = 0; j < 4; j++) { cv[j] = sh_c[r][kg * 4 + j]; c2v[j] = sh_c2[r][kg * 4 + j]; }
#pragma unroll
            for (int i = 0; i < 4; i++)
#pragma unroll
                for (int j = 0; j < 4; j++) {
                    am[i][j] = fmaf(hv[i], cv[j], am[i][j]);
                    as[i][j] = fmaf(h2[i], c2v[j], as[i][j]);
                }
        }
    }
#pragma unroll
    for (int i = 0; i < 4; i++)
#pragma unroll
        for (int j = 0; j < 4; j++) {
            int h = h0 + hg * 4 + i;
            int k = kg * 4 + j;
            g_pm[bb][k][h] = am[i][j];
            g_ps[bb][k][h] = as[i][j];
        }
}

// ---------------- stage 1b: counts[k] = rint(sum_b cluster[b,k]) ----------------
__global__ __launch_bounds__(1024) void counts_kernel(const float* __restrict__ cluster) {
    const int tid = (int)threadIdx.x;
    const int k = tid & 31;
    const int seg = tid >> 5;   // 0..31
    double a0 = 0, a1 = 0, a2 = 0, a3 = 0;
#pragma unroll 4
    for (int b = seg; b < BSZ; b += 128) {
        a0 += (double)cluster[b * KSZ + k];
        a1 += (double)cluster[(b + 32) * KSZ + k];
        a2 += (double)cluster[(b + 64) * KSZ + k];
        a3 += (double)cluster[(b + 96) * KSZ + k];
    }
    __shared__ double red[1024];
    red[tid] = a0 + a1 + a2 + a3;
    __syncthreads();
    for (int off = 512; off >= 32; off >>= 1) {
        if (tid < off) red[tid] += red[tid + off];
        __syncthreads();
    }
    if (tid < 32) g_counts[tid] = (float)rint(red[tid]);
}

// ---------------- stage 1c: reduce partials, form m and within ----------------
__global__ __launch_bounds__(256) void reduce_kernel() {
    int idx = blockIdx.x * 256 + (int)threadIdx.x;  // 0..16383
    int k = idx >> 9;
    int h = idx & 511;
    float sm = 0.f, ss = 0.f;
#pragma unroll
    for (int p = 0; p < 32; p++) {
        sm += g_pm[p][k][h];
        ss += g_ps[p][k][h];
    }
    g_m[k][h] = sm;
    // within = S2 + (B-2)*M^2   (exact algebraic identity of sum_b (s - M)^2)
    g_w[k][h] = ss + (float)(BSZ - 2) * sm * sm;
}

// ---------------- stage 2: regularized incomplete beta, I_x(a,b) ----------------
// NR-style Lentz continued fraction, f32 (accuracy analysis: tail side is the
// one feeding log1p, so f32 relative error ~1e-6 on T gives log error ~1e-6*T).
__device__ __forceinline__ float betacf_f(float a, float b, float x) {
    const float FPMIN = 1e-30f;
    float qab = a + b, qap = a + 1.0f, qam = a - 1.0f;
    float c = 1.0f;
    float d = 1.0f - qab * x / qap;
    if (fabsf(d) < FPMIN) d = FPMIN;
    d = 1.0f / d;
    float hh = d;
    for (int m = 1; m <= 200; m++) {
        float fm = (float)m, m2 = 2.0f * fm;
        float aa = fm * (b - fm) * x / ((qam + m2) * (a + m2));
        d = 1.0f + aa * d; if (fabsf(d) < FPMIN) d = FPMIN;
        c = 1.0f + aa / c; if (fabsf(c) < FPMIN) c = FPMIN;
        d = 1.0f / d;
        hh *= d * c;
        aa = -(a + fm) * (qab + fm) * x / ((a + m2) * (qap + m2));
        d = 1.0f + aa * d; if (fabsf(d) < FPMIN) d = FPMIN;
        c = 1.0f + aa / c; if (fabsf(c) < FPMIN) c = FPMIN;
        d = 1.0f / d;
        float del = d * c;
        hh *= del;
        if (fabsf(del - 1.0f) < 1e-7f) break;
    }
    return hh;
}

// one block per pair: compute log(betainc) for all H, then top-20 log-sum
__global__ __launch_bounds__(512) void pair_kernel() {
    int p = (int)blockIdx.x;
    int i = 0, rem = p;
    while (rem >= (KSZ - 1 - i)) { rem -= (KSZ - 1 - i); i++; }
    int j = i + 1 + rem;
    int h = (int)threadIdx.x;

    __shared__ double s_lbeta, s_b;
    __shared__ float s_ci, s_cj;
    if (h == 0) {
        float ci = g_counts[i], cj = g_counts[j];
        float d2 = (ci + cj) - 2.0f;
        if (d2 == 0.0f) d2 = d2 + 1e-5f;
        double b = 0.5 * (double)d2;
        s_b = b;
        s_ci = ci;
        s_cj = cj;
        // lbeta in DOUBLE: lgamma(~127) ~ 480, f32 ulp there is 3e-5 -> too coarse
        s_lbeta = lgamma(0.5) + lgamma(b) - lgamma(0.5 + b);
    }
    __syncthreads();
    const double b = s_b;
    const float bf = (float)b;
    const double lbeta = s_lbeta;

    float mi = g_m[i][h], mj = g_m[j][h];
    float wi = g_w[i][h], wj = g_w[j][h];
    float gm = 0.5f * (mi + mj);
    float di = mi - gm, dj = mj - gm;
    float between = di * di * s_ci + dj * dj * s_cj;
    float pw = wi + wj;
    float x = between / (between + pw);
    x = fminf(fmaxf(x, 1e-37f), 1.0f - 1e-5f);

    float lxf = logf(x);
    float l1mxf = log1pf(-x);
    double lbt = 0.5 * (double)lxf + b * (double)l1mxf - lbeta;

    double logI;
    double thresh = 1.5 / (b + 2.5);  // (a+1)/(a+b+2), a = 0.5
    if ((double)x < thresh) {
        // small side: I is small, log it directly
        float cf = betacf_f(0.5f, bf, x);
        logI = lbt + (double)logf(2.0f * cf);   // cf/a with a=0.5
    } else {
        // large side: compute the tail T = 1 - I accurately, logI = log1p(-T)
        float xc = 1.0f - x;
        float cf = betacf_f(bf, 0.5f, xc);
        float e = (float)lbt + logf(cf / bf);
        double T = (double)expf(e);             // underflow to 0 -> logI = 0, matches f32 ref
        logI = log1p(-T);
    }

    // ---- top-20 of 512 via 20 max-reductions (values are logs; monotone) ----
    __shared__ double sv[512];
    __shared__ double sred[512];
    __shared__ int s_claim;
    sv[h] = logI;
    double total = 0.0;
    for (int t = 0; t < DSZ; t++) {
        __syncthreads();
        sred[h] = sv[h];
        __syncthreads();
        for (int off = 256; off > 0; off >>= 1) {
            if (h < off) { double o = sred[h + off]; if (o > sred[h]) sred[h] = o; }
            __syncthreads();
        }
        double mx = sred[0];
        if (h == 0) s_claim = -1;
        __syncthreads();
        if (sv[h] == mx) atomicCAS(&s_claim, -1, h);  // claim exactly one on ties
        __syncthreads();
        if (h == s_claim) sv[h] = -1.0e300;
        total += mx;
    }
    if (h == 0) g_pair[p] = total;
}

// ---------------- stage 3: deterministic final sum ----------------
__global__ __launch_bounds__(512) void final_kernel(float* __restrict__ out) {
    int t = (int)threadIdx.x;
    __shared__ double red[512];
    red[t] = (t < NPAIR) ? g_pair[t] : 0.0;
    __syncthreads();
    for (int off = 256; off > 0; off >>= 1) {
        if (t < off) red[t] += red[t + off];
        __syncthreads();
    }
    if (t == 0) out[0] = (float)(-red[0]);
}

extern "C" void kernel_launch(void* const* d_in, const int* in_sizes, int n_in,
                              void* d_out, int out_size) {
    (void)in_sizes; (void)n_in; (void)out_size;
    const float* hidden  = (const float*)d_in[0];
    const float* cluster = (const float*)d_in[1];
    float* out = (float*)d_out;

    dim3 gA(32, 4);
    stats_kernel<<<gA, 256>>>(hidden, cluster);
    counts_kernel<<<1, 1024>>>(cluster);
    reduce_kernel<<<64, 256>>>();
    pair_kernel<<<NPAIR, 512>>>();
    final_kernel<<<1, 512>>>(out);
}

// round 2
// speedup vs baseline: 3.0228x; 3.0228x over previous
#include <cuda_runtime.h>
#include <math.h>

#define BSZ 4096
#define HSZ 512
#define KSZ 32
#define DSZ 20
#define NPAIR 496   // 32*31/2
#define NBB 64      // number of b-blocks in stage 1

// ---------------- device scratch (no allocations allowed) ----------------
__device__ float  g_pm[NBB][KSZ][HSZ];   // partial class sums          (4 MB)
__device__ float  g_ps[NBB][KSZ][HSZ];   // partial sum h^2 c^2         (4 MB)
__device__ double g_pcnt[NBB][KSZ];      // partial cluster column sums
__device__ float  g_m[KSZ][HSZ];         // class_sums^T [k][h]
__device__ float  g_w[KSZ][HSZ];         // within^T     [k][h]
__device__ float  g_counts[KSZ];
__device__ double g_pair[NPAIR];

// ---------------- stage 1: fused tall-skinny matmuls + counts partials ---
// grid (64 b-blocks, 4 h-blocks), 256 threads. Tile: 128h x 32k x 64b.
__global__ __launch_bounds__(256) void stats_kernel(const float* __restrict__ hidden,
                                                    const float* __restrict__ cluster) {
    const int bb = blockIdx.x;       // 0..63
    const int hb = blockIdx.y;       // 0..3
    const int h0 = hb * 128;
    const int b0 = bb * 64;
    const int tid = (int)threadIdx.x;
    const int hg = tid >> 3;         // 0..31 (owns 4 h)
    const int kg = tid & 7;          // 0..7  (owns 4 k)

    __shared__ float sh_hid[32][128];
    __shared__ float sh_c[32][KSZ];
    __shared__ float sh_c2[32][KSZ];

    float am[4][4], as[4][4];
#pragma unroll
    for (int i = 0; i < 4; i++)
#pragma unroll
        for (int j = 0; j < 4; j++) { am[i][j] = 0.f; as[i][j] = 0.f; }

    for (int bt = 0; bt < 64; bt += 32) {
        __syncthreads();
        // hidden tile: 32 rows x 128 cols = 1024 float4, 4 per thread
#pragma unroll
        for (int it = 0; it < 4; it++) {
            int e = tid + it * 256;          // float4 index
            int r = e >> 5, c4 = e & 31;
            float4 v = *(const float4*)&hidden[(b0 + bt + r) * HSZ + h0 + c4 * 4];
            *(float4*)&sh_hid[r][c4 * 4] = v;
        }
        // cluster tile: 32 rows x 32 cols = 256 float4, 1 per thread
        {
            int r = tid >> 3, c4 = tid & 7;
            float4 v = *(const float4*)&cluster[(b0 + bt + r) * KSZ + c4 * 4];
            *(float4*)&sh_c[r][c4 * 4] = v;
            float4 v2 = make_float4(v.x * v.x, v.y * v.y, v.z * v.z, v.w * v.w);
            *(float4*)&sh_c2[r][c4 * 4] = v2;
        }
        __syncthreads();
#pragma unroll 4
        for (int r = 0; r < 32; r++) {
            float hv[4], h2[4], cv[4], c2v[4];
#pragma unroll
            for (int i = 0; i < 4; i++) { hv[i] = sh_hid[r][hg * 4 + i]; h2[i] = hv[i] * hv[i]; }
#pragma unroll
            for (int j = 0; j < 4; j++) { cv[j] = sh_c[r][kg * 4 + j]; c2v[j] = sh_c2[r][kg * 4 + j]; }
#pragma unroll
            for (int i = 0; i < 4; i++)
#pragma unroll
                for (int j = 0; j < 4; j++) {
                    am[i][j] = fmaf(hv[i], cv[j], am[i][j]);
                    as[i][j] = fmaf(h2[i], c2v[j], as[i][j]);
                }
        }
    }
#pragma unroll
    for (int i = 0; i < 4; i++)
#pragma unroll
        for (int j = 0; j < 4; j++) {
            int h = h0 + hg * 4 + i;
            int k = kg * 4 + j;
            g_pm[bb][k][h] = am[i][j];
            g_ps[bb][k][h] = as[i][j];
        }

    // counts partials: only hb==0 blocks (one per b-block)
    if (hb == 0) {
        const int k = tid & 31;
        const int seg = tid >> 5;   // 0..7
        double s = 0.0;
#pragma unroll
        for (int r = seg; r < 64; r += 8)
            s += (double)cluster[(b0 + r) * KSZ + k];
        __shared__ double scnt[256];
        scnt[tid] = s;
        __syncthreads();
        if (tid < 128) scnt[tid] += scnt[tid + 128];
        __syncthreads();
        if (tid < 64) scnt[tid] += scnt[tid + 64];
        __syncthreads();
        if (tid < 32) g_pcnt[bb][tid] = scnt[tid] + scnt[tid + 32];
    }
}

// ---------------- stage 2: reduce partials -> m, within; finalize counts ----
__global__ __launch_bounds__(256) void reduce_kernel() {
    int idx = blockIdx.x * 256 + (int)threadIdx.x;  // 0..16383
    int k = idx >> 9;
    int h = idx & 511;
    float sm = 0.f, ss = 0.f;
#pragma unroll 8
    for (int p = 0; p < NBB; p++) {
        sm += g_pm[p][k][h];
        ss += g_ps[p][k][h];
    }
    g_m[k][h] = sm;
    // within = S2 + (B-2)*M^2  (exact identity for sum_b (s - M)^2, M = sum s)
    g_w[k][h] = ss + (float)(BSZ - 2) * sm * sm;

    if (blockIdx.x == 0 && threadIdx.x < KSZ) {
        double s = 0.0;
#pragma unroll 8
        for (int p = 0; p < NBB; p++) s += g_pcnt[p][threadIdx.x];
        g_counts[threadIdx.x] = (float)rint(s);
    }
}

// ---------------- Lentz continued fraction, warp-uniform convergence --------
__device__ __forceinline__ float betacf_warp(float a, float b, float x) {
    const float FPMIN = 1e-30f;
    float qab = a + b, qap = a + 1.0f, qam = a - 1.0f;
    float c = 1.0f;
    float d = 1.0f - qab * x / qap;
    if (fabsf(d) < FPMIN) d = FPMIN;
    d = 1.0f / d;
    float hh = d;
    bool done = false;
#pragma unroll 1
    for (int m = 1; m <= 200; m++) {
        if (!done) {
            float fm = (float)m, m2 = 2.0f * fm;
            float aa = fm * (b - fm) * x / ((qam + m2) * (a + m2));
            d = 1.0f + aa * d; if (fabsf(d) < FPMIN) d = FPMIN;
            c = 1.0f + aa / c; if (fabsf(c) < FPMIN) c = FPMIN;
            d = 1.0f / d;
            hh *= d * c;
            aa = -(a + fm) * (qab + fm) * x / ((a + m2) * (qap + m2));
            d = 1.0f + aa * d; if (fabsf(d) < FPMIN) d = FPMIN;
            c = 1.0f + aa / c; if (fabsf(c) < FPMIN) c = FPMIN;
            d = 1.0f / d;
            float del = d * c;
            hh *= del;
            if (fabsf(del - 1.0f) < 1e-7f) done = true;
        }
        if (__all_sync(0xffffffffu, done)) break;
    }
    return hh;
}

// ---------------- stage 3: per-pair x, top-20 by x (monotone), CF on 20 ----
__global__ __launch_bounds__(512) void pair_kernel() {
    int p = (int)blockIdx.x;
    int i = 0, rem = p;
    while (rem >= (KSZ - 1 - i)) { rem -= (KSZ - 1 - i); i++; }
    int j = i + 1 + rem;
    int h = (int)threadIdx.x;
    int lane = h & 31, warp = h >> 5;

    __shared__ double s_lbeta, s_bd;
    __shared__ float s_ci, s_cj, s_bf, s_thresh;
    __shared__ float sx[16 * 20];

    if (h == 0) {
        float ci = g_counts[i], cj = g_counts[j];
        float d2 = (ci + cj) - 2.0f;
        if (d2 == 0.0f) d2 = d2 + 1e-5f;
        double b = 0.5 * (double)d2;
        s_ci = ci; s_cj = cj;
        s_bd = b;
        s_bf = (float)b;
        s_thresh = 1.5f / ((float)b + 2.5f);   // (a+1)/(a+b+2), a=0.5
        s_lbeta = lgamma(0.5) + lgamma(b) - lgamma(0.5 + b);
    }
    __syncthreads();

    // ---- x for this (pair, h): cheap ----
    float ci = s_ci, cj = s_cj;
    float mi = g_m[i][h], mj = g_m[j][h];
    float wi = g_w[i][h], wj = g_w[j][h];
    float gm = 0.5f * (mi + mj);
    float di = mi - gm, dj = mj - gm;
    float between = di * di * ci + dj * dj * cj;
    float x = between / (between + wi + wj);
    x = fminf(fmaxf(x, 1e-37f), 1.0f - 1e-5f);

    // ---- per-warp bitonic sort DESCENDING (15 shfl steps, no barriers) ----
    float v = x;
#pragma unroll
    for (int kk = 2; kk <= 32; kk <<= 1)
#pragma unroll
        for (int jj = kk >> 1; jj > 0; jj >>= 1) {
            float o = __shfl_xor_sync(0xffffffffu, v, jj);
            bool up = ((lane & kk) == 0);
            bool lo = ((lane & jj) == 0);
            v = (up == lo) ? fmaxf(v, o) : fminf(v, o);   // descending
        }
    if (lane < 20) sx[warp * 20 + lane] = v;
    __syncthreads();
    if (warp != 0) return;   // only warp 0 continues (merge + CF)

    // ---- merge 320 candidates: 10 per lane, sorted, 20-step shfl-argmax ----
    float r[10];
#pragma unroll
    for (int q = 0; q < 10; q++) r[q] = sx[lane * 10 + q];
#pragma unroll
    for (int a = 0; a < 10; a++)
#pragma unroll
        for (int bq = 0; bq < 9 - a; bq++) {
            float x0 = r[bq], x1 = r[bq + 1];
            r[bq] = fmaxf(x0, x1); r[bq + 1] = fminf(x0, x1);
        }
    const float bf = s_bf;
    const float thresh = s_thresh;
    int ptr = 0;
    float head = r[0];
    float myx = 0.5f * thresh;   // dummy CF input for lanes >= 20
#pragma unroll 1
    for (int t = 0; t < DSZ; t++) {
        float mx = head;
#pragma unroll
        for (int off = 16; off; off >>= 1)
            mx = fmaxf(mx, __shfl_xor_sync(0xffffffffu, mx, off));
        int wl = (head == mx) ? lane : 32;
#pragma unroll
        for (int off = 16; off; off >>= 1)
            wl = min(wl, __shfl_xor_sync(0xffffffffu, wl, off));
        if (lane == wl) {
            ptr++;
            float nh = -1e38f;
#pragma unroll
            for (int q = 1; q < 10; q++) nh = (ptr == q) ? r[q] : nh;
            head = nh;
        }
        if (lane == t) myx = mx;
    }

    // ---- unified parameter-swapped CF on 20 lanes (lanes>=20 run dummies) --
    float xx = myx;
    bool sel = xx < thresh;
    float pa = sel ? 0.5f : bf;
    float pb = sel ? bf : 0.5f;
    float px = sel ? xx : (1.0f - xx);
    float cf = betacf_warp(pa, pb, px);

    double lbt = 0.5 * (double)logf(xx) + s_bd * (double)log1pf(-xx) - s_lbeta;
    double logI;
    if (sel) {
        logI = lbt + (double)logf(2.0f * cf);            // cf/a, a = 0.5
    } else {
        double T = exp(lbt + (double)logf(cf / bf));     // tail
        logI = (double)log1pf(-(float)T);
    }

    double contrib = (lane < DSZ) ? logI : 0.0;
#pragma unroll
    for (int off = 16; off; off >>= 1)
        contrib += __shfl_xor_sync(0xffffffffu, contrib, off);
    if (lane == 0) g_pair[p] = contrib;
}

// ---------------- stage 4: deterministic final sum ----------------
__global__ __launch_bounds__(512) void final_kernel(float* __restrict__ out) {
    int t = (int)threadIdx.x;
    __shared__ double red[512];
    red[t] = (t < NPAIR) ? g_pair[t] : 0.0;
    __syncthreads();
    for (int off = 256; off > 0; off >>= 1) {
        if (t < off) red[t] += red[t + off];
        __syncthreads();
    }
    if (t == 0) out[0] = (float)(-red[0]);
}

extern "C" void kernel_launch(void* const* d_in, const int* in_sizes, int n_in,
                              void* d_out, int out_size) {
    (void)in_sizes; (void)n_in; (void)out_size;
    const float* hidden  = (const float*)d_in[0];
    const float* cluster = (const float*)d_in[1];
    float* out = (float*)d_out;

    dim3 gA(NBB, 4);
    stats_kernel<<<gA, 256>>>(hidden, cluster);
    reduce_kernel<<<64, 256>>>();
    pair_kernel<<<NPAIR, 512>>>();
    final_kernel<<<1, 512>>>(out);
}

// round 3
// speedup vs baseline: 3.5050x; 1.1595x over previous
#include <cuda_runtime.h>
#include <math.h>

#define BSZ 4096
#define HSZ 512
#define KSZ 32
#define DSZ 20
#define NPAIR 496   // 32*31/2
#define NBB 64
#define GRID 256
#define TPB 256

// ---------------- device scratch (no allocations allowed) ----------------
__device__ float  g_pm[NBB][KSZ][HSZ];   // partial class sums
__device__ float  g_ps[NBB][KSZ][HSZ];   // partial sum h^2 c^2
__device__ double g_pcnt[NBB][KSZ];      // partial cluster column sums
__device__ float  g_m[KSZ][HSZ];         // class_sums^T [k][h]
__device__ float  g_w[KSZ][HSZ];         // within^T     [k][h]

struct PairMeta { float ci, cj, bf, thresh; double bd, lbeta; };
__device__ PairMeta g_meta[NPAIR];

__device__ unsigned long long g_acc;     // fixed-point (2^-32) loss accumulator
__device__ unsigned int g_done;

// software grid barrier (generation counter; never reset -> replay-safe)
__device__ unsigned int g_bar_count = 0;
__device__ volatile unsigned int g_bar_gen = 0;

__device__ __forceinline__ void grid_barrier() {
    __syncthreads();
    __threadfence();
    if (threadIdx.x == 0) {
        unsigned int gen = g_bar_gen;
        unsigned int t = atomicAdd(&g_bar_count, 1u);
        if (t == GRID - 1) {
            g_bar_count = 0u;
            __threadfence();
            g_bar_gen = gen + 1u;
        } else {
            while (g_bar_gen == gen) __nanosleep(64);
        }
    }
    __syncthreads();
    __threadfence();
}

// ---------------- Lentz continued fraction, warp-uniform convergence ------
__device__ __forceinline__ float betacf_warp(float a, float b, float x) {
    const float FPMIN = 1e-30f;
    float qab = a + b, qap = a + 1.0f, qam = a - 1.0f;
    float c = 1.0f;
    float d = 1.0f - qab * x / qap;
    if (fabsf(d) < FPMIN) d = FPMIN;
    d = 1.0f / d;
    float hh = d;
    bool done = false;
#pragma unroll 1
    for (int m = 1; m <= 200; m++) {
        if (!done) {
            float fm = (float)m, m2 = 2.0f * fm;
            float aa = fm * (b - fm) * x / ((qam + m2) * (a + m2));
            d = 1.0f + aa * d; if (fabsf(d) < FPMIN) d = FPMIN;
            c = 1.0f + aa / c; if (fabsf(c) < FPMIN) c = FPMIN;
            d = 1.0f / d;
            hh *= d * c;
            aa = -(a + fm) * (qab + fm) * x / ((a + m2) * (qap + m2));
            d = 1.0f + aa * d; if (fabsf(d) < FPMIN) d = FPMIN;
            c = 1.0f + aa / c; if (fabsf(c) < FPMIN) c = FPMIN;
            d = 1.0f / d;
            float del = d * c;
            hh *= del;
            if (fabsf(del - 1.0f) < 1e-7f) done = true;
        }
        if (__all_sync(0xffffffffu, done)) break;
    }
    return hh;
}

__device__ __forceinline__ void pair_ij(int p, int& ii, int& jj) {
    int i = 0, rem = p;
    while (rem >= (KSZ - 1 - i)) { rem -= (KSZ - 1 - i); i++; }
    ii = i; jj = i + 1 + rem;
}

// ---------------- the single fused kernel ----------------
__global__ __launch_bounds__(TPB, 2) void fused_kernel(const float* __restrict__ hidden,
                                                       const float* __restrict__ cluster,
                                                       float* __restrict__ out) {
    __shared__ union {
        struct {
            float hid[32][128];
            float c[32][KSZ];
            float c2[32][KSZ];
            double cnt[TPB];
        } s1;
        struct { float sx[2][320]; } s3;
    } sm;

    const int tid = (int)threadIdx.x;
    const int lane = tid & 31, warp = tid >> 5;

    // ================= Phase 1: fused tall-skinny matmuls =================
    {
        const int bb = (int)blockIdx.x & 63;   // 0..63
        const int hb = (int)blockIdx.x >> 6;   // 0..3
        const int h0 = hb * 128;
        const int b0 = bb * 64;
        const int hg = tid >> 3;               // owns 4 h
        const int kg = tid & 7;                // owns 4 k

        float am[4][4], as[4][4];
#pragma unroll
        for (int i = 0; i < 4; i++)
#pragma unroll
            for (int j = 0; j < 4; j++) { am[i][j] = 0.f; as[i][j] = 0.f; }

        for (int bt = 0; bt < 64; bt += 32) {
            __syncthreads();
#pragma unroll
            for (int it = 0; it < 4; it++) {
                int e = tid + it * 256;
                int r = e >> 5, c4 = e & 31;
                float4 v = *(const float4*)&hidden[(b0 + bt + r) * HSZ + h0 + c4 * 4];
                *(float4*)&sm.s1.hid[r][c4 * 4] = v;
            }
            {
                int r = tid >> 3, c4 = tid & 7;
                float4 v = *(const float4*)&cluster[(b0 + bt + r) * KSZ + c4 * 4];
                *(float4*)&sm.s1.c[r][c4 * 4] = v;
                float4 v2 = make_float4(v.x * v.x, v.y * v.y, v.z * v.z, v.w * v.w);
                *(float4*)&sm.s1.c2[r][c4 * 4] = v2;
            }
            __syncthreads();
#pragma unroll 4
            for (int r = 0; r < 32; r++) {
                float hv[4], h2[4], cv[4], c2v[4];
#pragma unroll
                for (int i = 0; i < 4; i++) { hv[i] = sm.s1.hid[r][hg * 4 + i]; h2[i] = hv[i] * hv[i]; }
#pragma unroll
                for (int j = 0; j < 4; j++) { cv[j] = sm.s1.c[r][kg * 4 + j]; c2v[j] = sm.s1.c2[r][kg * 4 + j]; }
#pragma unroll
                for (int i = 0; i < 4; i++)
#pragma unroll
                    for (int j = 0; j < 4; j++) {
                        am[i][j] = fmaf(hv[i], cv[j], am[i][j]);
                        as[i][j] = fmaf(h2[i], c2v[j], as[i][j]);
                    }
            }
        }
#pragma unroll
        for (int i = 0; i < 4; i++)
#pragma unroll
            for (int j = 0; j < 4; j++) {
                int h = h0 + hg * 4 + i;
                int k = kg * 4 + j;
                g_pm[bb][k][h] = am[i][j];
                g_ps[bb][k][h] = as[i][j];
            }

        // counts partials (one block row per bb)
        if (hb == 0) {
            const int k = tid & 31;
            const int seg = tid >> 5;
            double s = 0.0;
#pragma unroll
            for (int r = seg; r < 64; r += 8)
                s += (double)cluster[(b0 + r) * KSZ + k];
            __syncthreads();
            sm.s1.cnt[tid] = s;
            __syncthreads();
            if (tid < 128) sm.s1.cnt[tid] += sm.s1.cnt[tid + 128];
            __syncthreads();
            if (tid < 64) sm.s1.cnt[tid] += sm.s1.cnt[tid + 64];
            __syncthreads();
            if (tid < 32) g_pcnt[bb][tid] = sm.s1.cnt[tid] + sm.s1.cnt[tid + 32];
        }
    }

    grid_barrier();

    // ========== Phase 2: reduce partials -> m,w ; pair meta ; zero acc =====
    {
        int gt = (int)blockIdx.x * TPB + tid;
        if (gt < KSZ * HSZ) {
            int k = gt >> 9, h = gt & 511;
            float smm = 0.f, ss = 0.f;
#pragma unroll 8
            for (int p = 0; p < NBB; p++) {
                smm += g_pm[p][k][h];
                ss += g_ps[p][k][h];
            }
            g_m[k][h] = smm;
            g_w[k][h] = ss + (float)(BSZ - 2) * smm * smm;   // S2 + (B-2)M^2
        } else if (gt < KSZ * HSZ + NPAIR) {
            int p = gt - KSZ * HSZ;
            int ii, jj; pair_ij(p, ii, jj);
            double si = 0.0, sj = 0.0;
#pragma unroll 8
            for (int q = 0; q < NBB; q++) { si += g_pcnt[q][ii]; sj += g_pcnt[q][jj]; }
            float ci = (float)rint(si), cj = (float)rint(sj);
            float d2 = (ci + cj) - 2.0f;
            if (d2 == 0.0f) d2 += 1e-5f;
            double bd = 0.5 * (double)d2;
            PairMeta mt;
            mt.ci = ci; mt.cj = cj;
            mt.bf = (float)bd;
            mt.thresh = 1.5f / ((float)bd + 2.5f);           // (a+1)/(a+b+2), a=0.5
            mt.bd = bd;
            mt.lbeta = 0.57236494292470008707 + lgamma(bd) - lgamma(0.5 + bd); // lgamma(0.5)+...
            g_meta[p] = mt;
        } else if (gt == KSZ * HSZ + NPAIR) {
            g_acc = 0ULL;
            g_done = 0u;
        }
    }

    grid_barrier();

    // ================= Phase 3: pairs (x, top-20, CF) + final ==============
    {
        const int npair_here = ((int)blockIdx.x + GRID < NPAIR) ? 2 : 1;

        // all warps: compute x and per-warp sorted top-20s for both pairs
        for (int q = 0; q < npair_here; q++) {
            int p = (int)blockIdx.x + q * GRID;
            int ii, jj; pair_ij(p, ii, jj);
            float ci = g_meta[p].ci, cj = g_meta[p].cj;
#pragma unroll
            for (int half = 0; half < 2; half++) {
                int h = tid + half * 256;
                float mi = g_m[ii][h], mj = g_m[jj][h];
                float wi = g_w[ii][h], wj = g_w[jj][h];
                float gmv = 0.5f * (mi + mj);
                float di = mi - gmv, dj = mj - gmv;
                float between = di * di * ci + dj * dj * cj;
                float x = between / (between + wi + wj);
                x = fminf(fmaxf(x, 1e-37f), 1.0f - 1e-5f);
                // warp bitonic sort, descending
                float v = x;
#pragma unroll
                for (int kk = 2; kk <= 32; kk <<= 1)
#pragma unroll
                    for (int jjs = kk >> 1; jjs > 0; jjs >>= 1) {
                        float o = __shfl_xor_sync(0xffffffffu, v, jjs);
                        bool up = ((lane & kk) == 0);
                        bool lo = ((lane & jjs) == 0);
                        v = (up == lo) ? fmaxf(v, o) : fminf(v, o);
                    }
                if (lane < 20) sm.s3.sx[q][warp * 40 + half * 20 + lane] = v;
            }
        }
        __syncthreads();

        // warp0 merges pair A, warp1 merges pair B — concurrently
        if (warp < npair_here) {
            int p = (int)blockIdx.x + warp * GRID;
            PairMeta mt = g_meta[p];

            float r[10];
#pragma unroll
            for (int q = 0; q < 10; q++) r[q] = sm.s3.sx[warp][lane * 10 + q];
#pragma unroll
            for (int a = 0; a < 10; a++)
#pragma unroll
                for (int bq = 0; bq < 9 - a; bq++) {
                    float x0 = r[bq], x1 = r[bq + 1];
                    r[bq] = fmaxf(x0, x1); r[bq + 1] = fminf(x0, x1);
                }
            int ptr = 0;
            float head = r[0];
            float myx = 0.5f * mt.thresh;   // dummy CF input for lanes >= 20
#pragma unroll 1
            for (int t = 0; t < DSZ; t++) {
                float mx = head;
#pragma unroll
                for (int off = 16; off; off >>= 1)
                    mx = fmaxf(mx, __shfl_xor_sync(0xffffffffu, mx, off));
                int wl = (head == mx) ? lane : 32;
#pragma unroll
                for (int off = 16; off; off >>= 1)
                    wl = min(wl, __shfl_xor_sync(0xffffffffu, wl, off));
                if (lane == wl) {
                    ptr++;
                    float nh = -1e38f;
#pragma unroll
                    for (int q = 1; q < 10; q++) nh = (ptr == q) ? r[q] : nh;
                    head = nh;
                }
                if (lane == t) myx = mx;
            }

            // unified parameter-swapped CF on 20 lanes
            float xx = myx;
            bool sel = xx < mt.thresh;
            float pa = sel ? 0.5f : mt.bf;
            float pb = sel ? mt.bf : 0.5f;
            float px = sel ? xx : (1.0f - xx);
            float cf = betacf_warp(pa, pb, px);

            double lbt = 0.5 * (double)logf(xx) + mt.bd * (double)log1pf(-xx) - mt.lbeta;
            double logI;
            if (sel) {
                logI = lbt + (double)logf(2.0f * cf);          // cf/a, a = 0.5
            } else {
                double T = exp(lbt + (double)logf(cf / mt.bf));
                logI = (double)log1pf(-(float)T);
            }

            double contrib = (lane < DSZ) ? logI : 0.0;
#pragma unroll
            for (int off = 16; off; off >>= 1)
                contrib += __shfl_xor_sync(0xffffffffu, contrib, off);

            if (lane == 0) {
                long long fx = __double2ll_rn(contrib * 4294967296.0);
                atomicAdd(&g_acc, (unsigned long long)fx);
                __threadfence();
                unsigned int t = atomicAdd(&g_done, 1u);
                if (t == NPAIR - 1) {
                    long long total = (long long)atomicAdd(&g_acc, 0ULL);
                    out[0] = (float)(-(double)total * (1.0 / 4294967296.0));
                }
            }
        }
    }
}

extern "C" void kernel_launch(void* const* d_in, const int* in_sizes, int n_in,
                              void* d_out, int out_size) {
    (void)in_sizes; (void)n_in; (void)out_size;
    const float* hidden  = (const float*)d_in[0];
    const float* cluster = (const float*)d_in[1];
    float* out = (float*)d_out;
    fused_kernel<<<GRID, TPB>>>(hidden, cluster, out);
}

// round 4
// speedup vs baseline: 3.9349x; 1.1227x over previous
#include <cuda_runtime.h>
#include <math.h>

#define BSZ 4096
#define HSZ 512
#define KSZ 32
#define DSZ 20
#define NPAIR 496   // 32*31/2
#define NBB 64
#define GRID 256
#define TPB 256

// ---------------- device scratch (no allocations allowed) ----------------
__device__ float  g_pm[NBB][KSZ][HSZ];   // partial class sums
__device__ float  g_ps[NBB][KSZ][HSZ];   // partial sum h^2 c^2
__device__ double g_pcnt[NBB][KSZ];      // partial cluster column sums
__device__ float  g_m[KSZ][HSZ];         // class_sums^T [k][h]
__device__ float  g_w[KSZ][HSZ];         // within^T     [k][h]

struct PairMeta { float ci, cj, bf, thresh; double bd, lbeta; };
__device__ PairMeta g_meta[NPAIR];

__device__ unsigned long long g_acc;     // fixed-point (2^-32) loss accumulator
__device__ unsigned int g_done;

// software grid barrier (generation counter; never reset -> replay-safe)
__device__ unsigned int g_bar_count = 0;
__device__ volatile unsigned int g_bar_gen = 0;

__device__ __forceinline__ void grid_barrier() {
    __syncthreads();
    __threadfence();
    if (threadIdx.x == 0) {
        unsigned int gen = g_bar_gen;
        unsigned int t = atomicAdd(&g_bar_count, 1u);
        if (t == GRID - 1) {
            g_bar_count = 0u;
            __threadfence();
            g_bar_gen = gen + 1u;
        } else {
            while (g_bar_gen == gen) __nanosleep(64);
        }
    }
    __syncthreads();
    __threadfence();
}

// ln B(1/2, b) without lgamma: lnG(1/2) - ln( Gamma(b+1/2)/Gamma(b) ).
// Ratio via exact shift recurrence R(b) = R(b+1) * b/(b+1/2) up to z>=32,
// then asymptotic series (error ~1e-11 at z=32). ~30 DP ops + one log.
__device__ __forceinline__ double lbeta_half(double b) {
    double z = b;
    double prod = 1.0;
#pragma unroll 1
    while (z < 32.0) { prod *= z / (z + 0.5); z += 1.0; }
    double iz = 1.0 / z;
    double ser = 1.0 + iz * (-0.125 + iz * (0.0078125 +
                 iz * (0.0048828125 + iz * (-0.000640869140625))));
    return 0.57236494292470008707 - log(prod * sqrt(z) * ser);
}

// ---------------- Lentz continued fraction, warp-uniform convergence ------
__device__ __forceinline__ float betacf_warp(float a, float b, float x) {
    const float FPMIN = 1e-30f;
    float qab = a + b, qap = a + 1.0f, qam = a - 1.0f;
    float c = 1.0f;
    float d = 1.0f - qab * x / qap;
    if (fabsf(d) < FPMIN) d = FPMIN;
    d = 1.0f / d;
    float hh = d;
    bool done = false;
#pragma unroll 1
    for (int m = 1; m <= 200; m++) {
        if (!done) {
            float fm = (float)m, m2 = 2.0f * fm;
            float aa = fm * (b - fm) * x / ((qam + m2) * (a + m2));
            d = 1.0f + aa * d; if (fabsf(d) < FPMIN) d = FPMIN;
            c = 1.0f + aa / c; if (fabsf(c) < FPMIN) c = FPMIN;
            d = 1.0f / d;
            hh *= d * c;
            aa = -(a + fm) * (qab + fm) * x / ((a + m2) * (qap + m2));
            d = 1.0f + aa * d; if (fabsf(d) < FPMIN) d = FPMIN;
            c = 1.0f + aa / c; if (fabsf(c) < FPMIN) c = FPMIN;
            d = 1.0f / d;
            float del = d * c;
            hh *= del;
            if (fabsf(del - 1.0f) < 1e-7f) done = true;
        }
        if (__all_sync(0xffffffffu, done)) break;
    }
    return hh;
}

__device__ __forceinline__ void pair_ij(int p, int& ii, int& jj) {
    int i = 0, rem = p;
    while (rem >= (KSZ - 1 - i)) { rem -= (KSZ - 1 - i); i++; }
    ii = i; jj = i + 1 + rem;
}

// ---------------- the single fused kernel ----------------
__global__ __launch_bounds__(TPB, 2) void fused_kernel(const float* __restrict__ hidden,
                                                       const float* __restrict__ cluster,
                                                       float* __restrict__ out) {
    __shared__ union {
        struct {
            float hid[32][128];
            float c[32][KSZ];
            float c2[32][KSZ];
            double cnt[TPB];
        } s1;
        struct { float sx[2][320]; } s3;
    } sm;

    const int tid = (int)threadIdx.x;
    const int lane = tid & 31, warp = tid >> 5;

    // ================= Phase 1: fused tall-skinny matmuls =================
    {
        const int bb = (int)blockIdx.x & 63;   // 0..63
        const int hb = (int)blockIdx.x >> 6;   // 0..3
        const int h0 = hb * 128;
        const int b0 = bb * 64;
        const int hg = tid >> 3;               // owns 4 h
        const int kg = tid & 7;                // owns 4 k

        float am[4][4], as[4][4];
#pragma unroll
        for (int i = 0; i < 4; i++)
#pragma unroll
            for (int j = 0; j < 4; j++) { am[i][j] = 0.f; as[i][j] = 0.f; }

        for (int bt = 0; bt < 64; bt += 32) {
            __syncthreads();
#pragma unroll
            for (int it = 0; it < 4; it++) {
                int e = tid + it * 256;
                int r = e >> 5, c4 = e & 31;
                float4 v = *(const float4*)&hidden[(b0 + bt + r) * HSZ + h0 + c4 * 4];
                *(float4*)&sm.s1.hid[r][c4 * 4] = v;
            }
            {
                int r = tid >> 3, c4 = tid & 7;
                float4 v = *(const float4*)&cluster[(b0 + bt + r) * KSZ + c4 * 4];
                *(float4*)&sm.s1.c[r][c4 * 4] = v;
                float4 v2 = make_float4(v.x * v.x, v.y * v.y, v.z * v.z, v.w * v.w);
                *(float4*)&sm.s1.c2[r][c4 * 4] = v2;
            }
            __syncthreads();
#pragma unroll 4
            for (int r = 0; r < 32; r++) {
                float hv[4], h2[4], cv[4], c2v[4];
#pragma unroll
                for (int i = 0; i < 4; i++) { hv[i] = sm.s1.hid[r][hg * 4 + i]; h2[i] = hv[i] * hv[i]; }
#pragma unroll
                for (int j = 0; j < 4; j++) { cv[j] = sm.s1.c[r][kg * 4 + j]; c2v[j] = sm.s1.c2[r][kg * 4 + j]; }
#pragma unroll
                for (int i = 0; i < 4; i++)
#pragma unroll
                    for (int j = 0; j < 4; j++) {
                        am[i][j] = fmaf(hv[i], cv[j], am[i][j]);
                        as[i][j] = fmaf(h2[i], c2v[j], as[i][j]);
                    }
            }
        }
#pragma unroll
        for (int i = 0; i < 4; i++)
#pragma unroll
            for (int j = 0; j < 4; j++) {
                int h = h0 + hg * 4 + i;
                int k = kg * 4 + j;
                g_pm[bb][k][h] = am[i][j];
                g_ps[bb][k][h] = as[i][j];
            }

        // counts partials (one block row per bb)
        if (hb == 0) {
            const int k = tid & 31;
            const int seg = tid >> 5;
            double s = 0.0;
#pragma unroll
            for (int r = seg; r < 64; r += 8)
                s += (double)cluster[(b0 + r) * KSZ + k];
            __syncthreads();
            sm.s1.cnt[tid] = s;
            __syncthreads();
            if (tid < 128) sm.s1.cnt[tid] += sm.s1.cnt[tid + 128];
            __syncthreads();
            if (tid < 64) sm.s1.cnt[tid] += sm.s1.cnt[tid + 64];
            __syncthreads();
            if (tid < 32) g_pcnt[bb][tid] = sm.s1.cnt[tid] + sm.s1.cnt[tid + 32];
        }
    }

    grid_barrier();

    // ===== Phase 2: reduce partials -> m,w ; distributed pair meta =========
    {
        int gt = (int)blockIdx.x * TPB + tid;
        if (gt < KSZ * HSZ) {
            int k = gt >> 9, h = gt & 511;
            float smm = 0.f, ss = 0.f;
#pragma unroll 8
            for (int p = 0; p < NBB; p++) {
                smm += g_pm[p][k][h];
                ss += g_ps[p][k][h];
            }
            g_m[k][h] = smm;
            g_w[k][h] = ss + (float)(BSZ - 2) * smm * smm;   // S2 + (B-2)M^2
        }
        // pair meta: block bid handles pairs bid and bid+256 (warp0/warp1 lane0)
        if (warp < 2 && lane == 0) {
            int p = (int)blockIdx.x + warp * GRID;
            if (p < NPAIR) {
                int ii, jj; pair_ij(p, ii, jj);
                double si = 0.0, sj = 0.0;
#pragma unroll 8
                for (int q = 0; q < NBB; q++) { si += g_pcnt[q][ii]; sj += g_pcnt[q][jj]; }
                float ci = (float)rint(si), cj = (float)rint(sj);
                float d2 = (ci + cj) - 2.0f;
                if (d2 == 0.0f) d2 += 1e-5f;
                double bd = 0.5 * (double)d2;
                PairMeta mt;
                mt.ci = ci; mt.cj = cj;
                mt.bf = (float)bd;
                mt.thresh = 1.5f / ((float)bd + 2.5f);       // (a+1)/(a+b+2), a=0.5
                mt.bd = bd;
                mt.lbeta = lbeta_half(bd);
                g_meta[p] = mt;
            }
        }
        if (blockIdx.x == GRID - 1 && tid == TPB - 1) {
            g_acc = 0ULL;
            g_done = 0u;
        }
    }

    grid_barrier();

    // ================= Phase 3: pairs (x, top-20, CF) + final ==============
    {
        const int npair_here = ((int)blockIdx.x + GRID < NPAIR) ? 2 : 1;

        // all warps: compute x and per-warp sorted top-20s for both pairs
        for (int q = 0; q < npair_here; q++) {
            int p = (int)blockIdx.x + q * GRID;
            int ii, jj; pair_ij(p, ii, jj);
            float ci = g_meta[p].ci, cj = g_meta[p].cj;
#pragma unroll
            for (int half = 0; half < 2; half++) {
                int h = tid + half * 256;
                float mi = g_m[ii][h], mj = g_m[jj][h];
                float wi = g_w[ii][h], wj = g_w[jj][h];
                float gmv = 0.5f * (mi + mj);
                float di = mi - gmv, dj = mj - gmv;
                float between = di * di * ci + dj * dj * cj;
                float x = between / (between + wi + wj);
                x = fminf(fmaxf(x, 1e-37f), 1.0f - 1e-5f);
                // warp bitonic sort, descending
                float v = x;
#pragma unroll
                for (int kk = 2; kk <= 32; kk <<= 1)
#pragma unroll
                    for (int jjs = kk >> 1; jjs > 0; jjs >>= 1) {
                        float o = __shfl_xor_sync(0xffffffffu, v, jjs);
                        bool up = ((lane & kk) == 0);
                        bool lo = ((lane & jjs) == 0);
                        v = (up == lo) ? fmaxf(v, o) : fminf(v, o);
                    }
                if (lane < 20) sm.s3.sx[q][warp * 40 + half * 20 + lane] = v;
            }
        }
        __syncthreads();

        // warp0 merges pair A, warp1 merges pair B — concurrently
        if (warp < npair_here) {
            int p = (int)blockIdx.x + warp * GRID;
            PairMeta mt = g_meta[p];

            float r[10];
#pragma unroll
            for (int q = 0; q < 10; q++) r[q] = sm.s3.sx[warp][lane * 10 + q];
#pragma unroll
            for (int a = 0; a < 10; a++)
#pragma unroll
                for (int bq = 0; bq < 9 - a; bq++) {
                    float x0 = r[bq], x1 = r[bq + 1];
                    r[bq] = fmaxf(x0, x1); r[bq + 1] = fminf(x0, x1);
                }
            int ptr = 0;
            float head = r[0];
            float myx = 0.5f * mt.thresh;   // dummy CF input for lanes >= 20
#pragma unroll 1
            for (int t = 0; t < DSZ; t++) {
                float mx = head;
#pragma unroll
                for (int off = 16; off; off >>= 1)
                    mx = fmaxf(mx, __shfl_xor_sync(0xffffffffu, mx, off));
                int wl = (head == mx) ? lane : 32;
#pragma unroll
                for (int off = 16; off; off >>= 1)
                    wl = min(wl, __shfl_xor_sync(0xffffffffu, wl, off));
                if (lane == wl) {
                    ptr++;
                    float nh = -1e38f;
#pragma unroll
                    for (int q = 1; q < 10; q++) nh = (ptr == q) ? r[q] : nh;
                    head = nh;
                }
                if (lane == t) myx = mx;
            }

            // unified parameter-swapped CF on 20 lanes
            float xx = myx;
            bool sel = xx < mt.thresh;
            float pa = sel ? 0.5f : mt.bf;
            float pb = sel ? mt.bf : 0.5f;
            float px = sel ? xx : (1.0f - xx);
            float cf = betacf_warp(pa, pb, px);

            double lbt = 0.5 * (double)logf(xx) + mt.bd * (double)log1pf(-xx) - mt.lbeta;
            double logI;
            if (sel) {
                logI = lbt + (double)logf(2.0f * cf);          // cf/a, a = 0.5
            } else {
                double T = exp(lbt + (double)logf(cf / mt.bf));
                logI = (double)log1pf(-(float)T);
            }

            double contrib = (lane < DSZ) ? logI : 0.0;
#pragma unroll
            for (int off = 16; off; off >>= 1)
                contrib += __shfl_xor_sync(0xffffffffu, contrib, off);

            if (lane == 0) {
                long long fx = __double2ll_rn(contrib * 4294967296.0);
                atomicAdd(&g_acc, (unsigned long long)fx);
                __threadfence();
                unsigned int t = atomicAdd(&g_done, 1u);
                if (t == NPAIR - 1) {
                    long long total = (long long)atomicAdd(&g_acc, 0ULL);
                    out[0] = (float)(-(double)total * (1.0 / 4294967296.0));
                }
            }
        }
    }
}

extern "C" void kernel_launch(void* const* d_in, const int* in_sizes, int n_in,
                              void* d_out, int out_size) {
    (void)in_sizes; (void)n_in; (void)out_size;
    const float* hidden  = (const float*)d_in[0];
    const float* cluster = (const float*)d_in[1];
    float* out = (float*)d_out;
    fused_kernel<<<GRID, TPB>>>(hidden, cluster, out);
}

// round 5
// speedup vs baseline: 4.2710x; 1.0854x over previous
#include <cuda_runtime.h>
#include <math.h>

#define BSZ 4096
#define HSZ 512
#define KSZ 32
#define DSZ 20
#define NPAIR 496   // 32*31/2
#define NBB 64
#define GRID 256
#define TPB 256

// ---------------- device scratch (no allocations allowed) ----------------
// [bb][h][k] layout: phase-1 stores are float4, fully coalesced.
__device__ float  g_pm[NBB][HSZ][KSZ];
__device__ float  g_ps[NBB][HSZ][KSZ];
__device__ double g_pcnt[NBB][KSZ];
__device__ float  g_m[KSZ][HSZ];         // class_sums^T [k][h]
__device__ float  g_w[KSZ][HSZ];         // within^T     [k][h]

struct PairMeta { float ci, cj, bf, thresh; double bd, lbeta; };
__device__ PairMeta g_meta[NPAIR];

__device__ unsigned long long g_acc;     // fixed-point (2^-32) loss accumulator
__device__ unsigned int g_done;

// software grid barrier (generation counter; never reset -> replay-safe)
__device__ unsigned int g_bar_count = 0;
__device__ volatile unsigned int g_bar_gen = 0;

__device__ __forceinline__ void grid_barrier() {
    __syncthreads();
    __threadfence();
    if (threadIdx.x == 0) {
        unsigned int gen = g_bar_gen;
        unsigned int t = atomicAdd(&g_bar_count, 1u);
        if (t == GRID - 1) {
            g_bar_count = 0u;
            __threadfence();
            g_bar_gen = gen + 1u;
        } else {
            while (g_bar_gen == gen) __nanosleep(64);
        }
    }
    __syncthreads();
    __threadfence();
}

// ln B(1/2, b) without lgamma: ratio Gamma(b+1/2)/Gamma(b) via shift
// recurrence to z>=32 + asymptotic series (err ~1e-11).
__device__ __forceinline__ double lbeta_half(double b) {
    double z = b;
    double prod = 1.0;
#pragma unroll 1
    while (z < 32.0) { prod *= z / (z + 0.5); z += 1.0; }
    double iz = 1.0 / z;
    double ser = 1.0 + iz * (-0.125 + iz * (0.0078125 +
                 iz * (0.0048828125 + iz * (-0.000640869140625))));
    return 0.57236494292470008707 - log(prod * sqrt(z) * ser);
}

// ---------------- Lentz continued fraction, warp-uniform convergence ------
__device__ __forceinline__ float betacf_warp(float a, float b, float x) {
    const float FPMIN = 1e-30f;
    float qab = a + b, qap = a + 1.0f, qam = a - 1.0f;
    float c = 1.0f;
    float d = 1.0f - qab * x / qap;
    if (fabsf(d) < FPMIN) d = FPMIN;
    d = 1.0f / d;
    float hh = d;
    bool done = false;
#pragma unroll 1
    for (int m = 1; m <= 200; m++) {
        if (!done) {
            float fm = (float)m, m2 = 2.0f * fm;
            float aa = fm * (b - fm) * x / ((qam + m2) * (a + m2));
            d = 1.0f + aa * d; if (fabsf(d) < FPMIN) d = FPMIN;
            c = 1.0f + aa / c; if (fabsf(c) < FPMIN) c = FPMIN;
            d = 1.0f / d;
            hh *= d * c;
            aa = -(a + fm) * (qab + fm) * x / ((a + m2) * (qap + m2));
            d = 1.0f + aa * d; if (fabsf(d) < FPMIN) d = FPMIN;
            c = 1.0f + aa / c; if (fabsf(c) < FPMIN) c = FPMIN;
            d = 1.0f / d;
            float del = d * c;
            hh *= del;
            if (fabsf(del - 1.0f) < 1e-7f) done = true;
        }
        if (__all_sync(0xffffffffu, done)) break;
    }
    return hh;
}

__device__ __forceinline__ void pair_ij(int p, int& ii, int& jj) {
    int i = 0, rem = p;
    while (rem >= (KSZ - 1 - i)) { rem -= (KSZ - 1 - i); i++; }
    ii = i; jj = i + 1 + rem;
}

// ---------------- the single fused kernel ----------------
__global__ __launch_bounds__(TPB, 2) void fused_kernel(const float* __restrict__ hidden,
                                                       const float* __restrict__ cluster,
                                                       float* __restrict__ out) {
    __shared__ union {
        struct {
            float hid[32][128];
            float hid2[32][128];
            float c[32][KSZ];
            float c2[32][KSZ];
            double cnt[TPB];
        } s1;
        struct { float sx[2][320]; } s3;
    } sm;

    const int tid = (int)threadIdx.x;
    const int lane = tid & 31, warp = tid >> 5;

    // ================= Phase 1: fused tall-skinny matmuls =================
    {
        const int bb = (int)blockIdx.x & 63;   // 0..63
        const int hb = (int)blockIdx.x >> 6;   // 0..3
        const int h0 = hb * 128;
        const int b0 = bb * 64;
        const int hg = tid >> 3;               // owns 4 h
        const int kg = tid & 7;                // owns 4 k

        float am[4][4], as[4][4];
#pragma unroll
        for (int i = 0; i < 4; i++)
#pragma unroll
            for (int j = 0; j < 4; j++) { am[i][j] = 0.f; as[i][j] = 0.f; }

        for (int bt = 0; bt < 64; bt += 32) {
            __syncthreads();
#pragma unroll
            for (int it = 0; it < 4; it++) {
                int e = tid + it * 256;
                int r = e >> 5, c4 = e & 31;
                float4 v = *(const float4*)&hidden[(b0 + bt + r) * HSZ + h0 + c4 * 4];
                *(float4*)&sm.s1.hid[r][c4 * 4] = v;
                float4 v2 = make_float4(v.x * v.x, v.y * v.y, v.z * v.z, v.w * v.w);
                *(float4*)&sm.s1.hid2[r][c4 * 4] = v2;
            }
            {
                int r = tid >> 3, c4 = tid & 7;
                float4 v = *(const float4*)&cluster[(b0 + bt + r) * KSZ + c4 * 4];
                *(float4*)&sm.s1.c[r][c4 * 4] = v;
                float4 v2 = make_float4(v.x * v.x, v.y * v.y, v.z * v.z, v.w * v.w);
                *(float4*)&sm.s1.c2[r][c4 * 4] = v2;
            }
            __syncthreads();
#pragma unroll 4
            for (int r = 0; r < 32; r++) {
                float hv[4], h2[4], cv[4], c2v[4];
#pragma unroll
                for (int i = 0; i < 4; i++) { hv[i] = sm.s1.hid[r][hg * 4 + i]; h2[i] = sm.s1.hid2[r][hg * 4 + i]; }
#pragma unroll
                for (int j = 0; j < 4; j++) { cv[j] = sm.s1.c[r][kg * 4 + j]; c2v[j] = sm.s1.c2[r][kg * 4 + j]; }
#pragma unroll
                for (int i = 0; i < 4; i++)
#pragma unroll
                    for (int j = 0; j < 4; j++) {
                        am[i][j] = fmaf(hv[i], cv[j], am[i][j]);
                        as[i][j] = fmaf(h2[i], c2v[j], as[i][j]);
                    }
            }
        }
        // coalesced float4 stores: [bb][h][k], 4 consecutive k per thread
#pragma unroll
        for (int i = 0; i < 4; i++) {
            int h = h0 + hg * 4 + i;
            *(float4*)&g_pm[bb][h][kg * 4] = make_float4(am[i][0], am[i][1], am[i][2], am[i][3]);
            *(float4*)&g_ps[bb][h][kg * 4] = make_float4(as[i][0], as[i][1], as[i][2], as[i][3]);
        }

        // counts partials (one block row per bb)
        if (hb == 0) {
            const int k = tid & 31;
            const int seg = tid >> 5;
            double s = 0.0;
#pragma unroll
            for (int r = seg; r < 64; r += 8)
                s += (double)cluster[(b0 + r) * KSZ + k];
            __syncthreads();
            sm.s1.cnt[tid] = s;
            __syncthreads();
            if (tid < 128) sm.s1.cnt[tid] += sm.s1.cnt[tid + 128];
            __syncthreads();
            if (tid < 64) sm.s1.cnt[tid] += sm.s1.cnt[tid + 64];
            __syncthreads();
            if (tid < 32) g_pcnt[bb][tid] = sm.s1.cnt[tid] + sm.s1.cnt[tid + 32];
        }
    }

    grid_barrier();

    // ===== Phase 2: reduce partials -> m,w ; distributed pair meta =========
    {
        int gt = (int)blockIdx.x * TPB + tid;
        if (gt < 2 * KSZ * HSZ) {              // blocks 0..127, 2 threads/cell
            int cell = gt >> 1;                // 0..16383
            int half = gt & 1;
            int k = cell & 31;
            int h = cell >> 5;
            float smm = 0.f, ss = 0.f;
            int p0 = half * 32;
#pragma unroll 8
            for (int p = p0; p < p0 + 32; p++) {
                smm += g_pm[p][h][k];
                ss  += g_ps[p][h][k];
            }
            float smo = __shfl_xor_sync(0xffffffffu, smm, 1);
            float sso = __shfl_xor_sync(0xffffffffu, ss, 1);
            if (half == 0) {                    // fixed order: half0 + half1
                float M = smm + smo;
                float S2 = ss + sso;
                g_m[k][h] = M;
                g_w[k][h] = S2 + (float)(BSZ - 2) * M * M;   // S2 + (B-2)M^2
            }
        }
        // pair meta: block bid handles pairs bid and bid+256 (warp0/warp1 lane0)
        if (warp < 2 && lane == 0) {
            int p = (int)blockIdx.x + warp * GRID;
            if (p < NPAIR) {
                int ii, jj; pair_ij(p, ii, jj);
                double si = 0.0, sj = 0.0;
#pragma unroll 8
                for (int q = 0; q < NBB; q++) { si += g_pcnt[q][ii]; sj += g_pcnt[q][jj]; }
                float ci = (float)rint(si), cj = (float)rint(sj);
                float d2 = (ci + cj) - 2.0f;
                if (d2 == 0.0f) d2 += 1e-5f;
                double bd = 0.5 * (double)d2;
                PairMeta mt;
                mt.ci = ci; mt.cj = cj;
                mt.bf = (float)bd;
                mt.thresh = 1.5f / ((float)bd + 2.5f);       // (a+1)/(a+b+2), a=0.5
                mt.bd = bd;
                mt.lbeta = lbeta_half(bd);
                g_meta[p] = mt;
            }
        }
        if (blockIdx.x == GRID - 1 && tid == TPB - 1) {
            g_acc = 0ULL;
            g_done = 0u;
        }
    }

    grid_barrier();

    // ================= Phase 3: pairs (x, top-20, CF) + final ==============
    {
        const int npair_here = ((int)blockIdx.x + GRID < NPAIR) ? 2 : 1;

        for (int q = 0; q < npair_here; q++) {
            int p = (int)blockIdx.x + q * GRID;
            int ii, jj; pair_ij(p, ii, jj);
            float ci = g_meta[p].ci, cj = g_meta[p].cj;
#pragma unroll
            for (int half = 0; half < 2; half++) {
                int h = tid + half * 256;
                float mi = g_m[ii][h], mj = g_m[jj][h];
                float wi = g_w[ii][h], wj = g_w[jj][h];
                float gmv = 0.5f * (mi + mj);
                float di = mi - gmv, dj = mj - gmv;
                float between = di * di * ci + dj * dj * cj;
                float x = between / (between + wi + wj);
                x = fminf(fmaxf(x, 1e-37f), 1.0f - 1e-5f);
                // warp bitonic sort, descending
                float v = x;
#pragma unroll
                for (int kk = 2; kk <= 32; kk <<= 1)
#pragma unroll
                    for (int jjs = kk >> 1; jjs > 0; jjs >>= 1) {
                        float o = __shfl_xor_sync(0xffffffffu, v, jjs);
                        bool up = ((lane & kk) == 0);
                        bool lo = ((lane & jjs) == 0);
                        v = (up == lo) ? fmaxf(v, o) : fminf(v, o);
                    }
                if (lane < 20) sm.s3.sx[q][warp * 40 + half * 20 + lane] = v;
            }
        }
        __syncthreads();

        // warp0 merges pair A, warp1 merges pair B — concurrently
        if (warp < npair_here) {
            int p = (int)blockIdx.x + warp * GRID;
            PairMeta mt = g_meta[p];

            float r[10];
#pragma unroll
            for (int q = 0; q < 10; q++) r[q] = sm.s3.sx[warp][lane * 10 + q];
#pragma unroll
            for (int a = 0; a < 10; a++)
#pragma unroll
                for (int bq = 0; bq < 9 - a; bq++) {
                    float x0 = r[bq], x1 = r[bq + 1];
                    r[bq] = fmaxf(x0, x1); r[bq + 1] = fminf(x0, x1);
                }
            int ptr = 0;
            float head = r[0];
            float myx = 0.5f * mt.thresh;   // dummy CF input for lanes >= 20
#pragma unroll 1
            for (int t = 0; t < DSZ; t++) {
                float mx = head;
#pragma unroll
                for (int off = 16; off; off >>= 1)
                    mx = fmaxf(mx, __shfl_xor_sync(0xffffffffu, mx, off));
                int wl = (head == mx) ? lane : 32;
#pragma unroll
                for (int off = 16; off; off >>= 1)
                    wl = min(wl, __shfl_xor_sync(0xffffffffu, wl, off));
                if (lane == wl) {
                    ptr++;
                    float nh = -1e38f;
#pragma unroll
                    for (int q = 1; q < 10; q++) nh = (ptr == q) ? r[q] : nh;
                    head = nh;
                }
                if (lane == t) myx = mx;
            }

            // unified parameter-swapped CF on 20 lanes
            float xx = myx;
            bool sel = xx < mt.thresh;
            float pa = sel ? 0.5f : mt.bf;
            float pb = sel ? mt.bf : 0.5f;
            float px = sel ? xx : (1.0f - xx);
            float cf = betacf_warp(pa, pb, px);

            double lbt = 0.5 * (double)logf(xx) + mt.bd * (double)log1pf(-xx) - mt.lbeta;
            double logI;
            if (sel) {
                logI = lbt + (double)logf(2.0f * cf);          // cf/a, a = 0.5
            } else {
                double T = exp(lbt + (double)logf(cf / mt.bf));
                logI = (double)log1pf(-(float)T);
            }

            double contrib = (lane < DSZ) ? logI : 0.0;
#pragma unroll
            for (int off = 16; off; off >>= 1)
                contrib += __shfl_xor_sync(0xffffffffu, contrib, off);

            if (lane == 0) {
                long long fx = __double2ll_rn(contrib * 4294967296.0);
                atomicAdd(&g_acc, (unsigned long long)fx);
                __threadfence();
                unsigned int t = atomicAdd(&g_done, 1u);
                if (t == NPAIR - 1) {
                    long long total = (long long)atomicAdd(&g_acc, 0ULL);
                    out[0] = (float)(-(double)total * (1.0 / 4294967296.0));
                }
            }
        }
    }
}

extern "C" void kernel_launch(void* const* d_in, const int* in_sizes, int n_in,
                              void* d_out, int out_size) {
    (void)in_sizes; (void)n_in; (void)out_size;
    const float* hidden  = (const float*)d_in[0];
    const float* cluster = (const float*)d_in[1];
    float* out = (float*)d_out;
    fused_kernel<<<GRID, TPB>>>(hidden, cluster, out);
}

// round 6
// speedup vs baseline: 4.3292x; 1.0136x over previous
#include <cuda_runtime.h>
#include <math.h>

#define BSZ 4096
#define HSZ 512
#define KSZ 32
#define DSZ 20
#define NPAIR 496   // 32*31/2
#define NBB 64
#define GRID 256
#define TPB 256

typedef unsigned long long u64;

// ---------------- device scratch (no allocations allowed) ----------------
__device__ float  g_pm[NBB][HSZ][KSZ];   // partial class sums  [bb][h][k]
__device__ float  g_ps[NBB][HSZ][KSZ];   // partial sum h^2c^2  [bb][h][k]
__device__ double g_pcnt[NBB][KSZ];
__device__ float  g_m[KSZ][HSZ];
__device__ float  g_w[KSZ][HSZ];
__device__ float  g_inv[4096];           // 1/j reciprocal table

struct PairMeta { float ci, cj, bf, thresh; double bd, lbeta; int nu, odd; };
__device__ PairMeta g_meta[NPAIR];

__device__ unsigned long long g_acc;     // fixed-point (2^-32) accumulator
__device__ unsigned int g_done;

__device__ unsigned int g_bar_count = 0;
__device__ volatile unsigned int g_bar_gen = 0;

__device__ __forceinline__ void grid_barrier() {
    __syncthreads();
    __threadfence();
    if (threadIdx.x == 0) {
        unsigned int gen = g_bar_gen;
        unsigned int t = atomicAdd(&g_bar_count, 1u);
        if (t == GRID - 1) {
            g_bar_count = 0u;
            __threadfence();
            g_bar_gen = gen + 1u;
        } else {
            while (g_bar_gen == gen) __nanosleep(64);
        }
    }
    __syncthreads();
    __threadfence();
}

__device__ __forceinline__ u64 ffma2(u64 a, u64 b, u64 c) {
    u64 d;
    asm("fma.rn.f32x2 %0, %1, %2, %3;" : "=l"(d) : "l"(a), "l"(b), "l"(c));
    return d;
}
__device__ __forceinline__ float f2lo(u64 v) { return __uint_as_float((unsigned)v); }
__device__ __forceinline__ float f2hi(u64 v) { return __uint_as_float((unsigned)(v >> 32)); }

union F4U { float4 f; u64 d[2]; };

// ln B(1/2, b): ratio Gamma(b+1/2)/Gamma(b) via shift recurrence + asymptotic.
__device__ __forceinline__ double lbeta_half(double b) {
    double z = b, prod = 1.0;
#pragma unroll 1
    while (z < 32.0) { prod *= z / (z + 0.5); z += 1.0; }
    double iz = 1.0 / z;
    double ser = 1.0 + iz * (-0.125 + iz * (0.0078125 +
                 iz * (0.0048828125 + iz * (-0.000640869140625))));
    return 0.57236494292470008707 - log(prod * sqrt(z) * ser);
}

// Lentz CF fallback (non-integer nu only), warp-uniform, f32-safe tolerance.
__device__ __forceinline__ float betacf_warp(float a, float b, float x) {
    const float FPMIN = 1e-30f;
    float qab = a + b, qap = a + 1.0f, qam = a - 1.0f;
    float c = 1.0f;
    float d = 1.0f - qab * x / qap;
    if (fabsf(d) < FPMIN) d = FPMIN;
    d = 1.0f / d;
    float hh = d;
    bool done = false;
#pragma unroll 1
    for (int m = 1; m <= 200; m++) {
        if (!done) {
            float fm = (float)m, m2 = 2.0f * fm;
            float aa = fm * (b - fm) * x / ((qam + m2) * (a + m2));
            d = 1.0f + aa * d; if (fabsf(d) < FPMIN) d = FPMIN;
            c = 1.0f + aa / c; if (fabsf(c) < FPMIN) c = FPMIN;
            d = 1.0f / d;
            hh *= d * c;
            aa = -(a + fm) * (qab + fm) * x / ((a + m2) * (qap + m2));
            d = 1.0f + aa * d; if (fabsf(d) < FPMIN) d = FPMIN;
            c = 1.0f + aa / c; if (fabsf(c) < FPMIN) c = FPMIN;
            d = 1.0f / d;
            float del = d * c;
            hh *= del;
            if (fabsf(del - 1.0f) < 2.4e-7f) done = true;
        }
        if (__all_sync(0xffffffffu, done)) break;
    }
    return hh;
}

__device__ __forceinline__ void pair_ij(int p, int& ii, int& jj) {
    int i = 0, rem = p;
    while (rem >= (KSZ - 1 - i)) { rem -= (KSZ - 1 - i); i++; }
    ii = i; jj = i + 1 + rem;
}

// ---------------- the single fused kernel ----------------
__global__ __launch_bounds__(TPB, 2) void fused_kernel(const float* __restrict__ hidden,
                                                       const float* __restrict__ cluster,
                                                       float* __restrict__ out) {
    __shared__ union {
        struct {
            float hidp[32][256];   // packed pairs {h, h^2}
            float cp[32][64];      // packed pairs {c, c^2}
            double cnt[TPB];
        } s1;
        struct { float sx[2][320]; } s3;
    } sm;

    const int tid = (int)threadIdx.x;
    const int lane = tid & 31, warp = tid >> 5;

    // ================= Phase 1: packed-FFMA2 tall-skinny matmuls ===========
    {
        const int bb = (int)blockIdx.x & 63;
        const int hb = (int)blockIdx.x >> 6;
        const int h0 = hb * 128;
        const int b0 = bb * 64;
        const int hg = tid >> 3;               // owns 4 h
        const int kg = tid & 7;                // owns 4 k

        u64 acc[4][4];
#pragma unroll
        for (int i = 0; i < 4; i++)
#pragma unroll
            for (int j = 0; j < 4; j++) acc[i][j] = 0ULL;

        for (int bt = 0; bt < 64; bt += 32) {
            __syncthreads();
#pragma unroll
            for (int it = 0; it < 4; it++) {
                int e = tid + it * 256;
                int r = e >> 5, c4 = e & 31;
                float4 v = *(const float4*)&hidden[(b0 + bt + r) * HSZ + h0 + c4 * 4];
                float4 w0 = make_float4(v.x, v.x * v.x, v.y, v.y * v.y);
                float4 w1 = make_float4(v.z, v.z * v.z, v.w, v.w * v.w);
                *(float4*)&sm.s1.hidp[r][c4 * 8] = w0;
                *(float4*)&sm.s1.hidp[r][c4 * 8 + 4] = w1;
            }
            {
                int r = tid >> 3, c4 = tid & 7;
                float4 v = *(const float4*)&cluster[(b0 + bt + r) * KSZ + c4 * 4];
                float4 w0 = make_float4(v.x, v.x * v.x, v.y, v.y * v.y);
                float4 w1 = make_float4(v.z, v.z * v.z, v.w, v.w * v.w);
                *(float4*)&sm.s1.cp[r][c4 * 8] = w0;
                *(float4*)&sm.s1.cp[r][c4 * 8 + 4] = w1;
            }
            __syncthreads();
#pragma unroll 4
            for (int r = 0; r < 32; r++) {
                F4U qh0, qh1, qc0, qc1;
                qh0.f = *(const float4*)&sm.s1.hidp[r][hg * 8];
                qh1.f = *(const float4*)&sm.s1.hidp[r][hg * 8 + 4];
                qc0.f = *(const float4*)&sm.s1.cp[r][kg * 8];
                qc1.f = *(const float4*)&sm.s1.cp[r][kg * 8 + 4];
                u64 hp[4] = { qh0.d[0], qh0.d[1], qh1.d[0], qh1.d[1] };
                u64 cpk[4] = { qc0.d[0], qc0.d[1], qc1.d[0], qc1.d[1] };
#pragma unroll
                for (int i = 0; i < 4; i++)
#pragma unroll
                    for (int j = 0; j < 4; j++)
                        acc[i][j] = ffma2(hp[i], cpk[j], acc[i][j]);
            }
        }
#pragma unroll
        for (int i = 0; i < 4; i++) {
            int h = h0 + hg * 4 + i;
            float4 pm4 = make_float4(f2lo(acc[i][0]), f2lo(acc[i][1]), f2lo(acc[i][2]), f2lo(acc[i][3]));
            float4 ps4 = make_float4(f2hi(acc[i][0]), f2hi(acc[i][1]), f2hi(acc[i][2]), f2hi(acc[i][3]));
            *(float4*)&g_pm[bb][h][kg * 4] = pm4;
            *(float4*)&g_ps[bb][h][kg * 4] = ps4;
        }

        // counts partials (one block row per bb)
        if (hb == 0) {
            const int k = tid & 31;
            const int seg = tid >> 5;
            double s = 0.0;
#pragma unroll
            for (int r = seg; r < 64; r += 8)
                s += (double)cluster[(b0 + r) * KSZ + k];
            __syncthreads();
            sm.s1.cnt[tid] = s;
            __syncthreads();
            if (tid < 128) sm.s1.cnt[tid] += sm.s1.cnt[tid + 128];
            __syncthreads();
            if (tid < 64) sm.s1.cnt[tid] += sm.s1.cnt[tid + 64];
            __syncthreads();
            if (tid < 32) g_pcnt[bb][tid] = sm.s1.cnt[tid] + sm.s1.cnt[tid + 32];
        }
    }

    grid_barrier();

    // ===== Phase 2: reduce -> m,w ; pair meta ; reciprocal table ===========
    {
        int gt = (int)blockIdx.x * TPB + tid;
        if (gt < 2 * KSZ * HSZ) {              // blocks 0..127
            int cell = gt >> 1;
            int half = gt & 1;
            int k = cell & 31;
            int h = cell >> 5;
            float smm = 0.f, ss = 0.f;
            int p0 = half * 32;
#pragma unroll 8
            for (int p = p0; p < p0 + 32; p++) {
                smm += g_pm[p][h][k];
                ss  += g_ps[p][h][k];
            }
            float smo = __shfl_xor_sync(0xffffffffu, smm, 1);
            float sso = __shfl_xor_sync(0xffffffffu, ss, 1);
            if (half == 0) {
                float M = smm + smo;
                float S2 = ss + sso;
                g_m[k][h] = M;
                g_w[k][h] = S2 + (float)(BSZ - 2) * M * M;
            }
        } else if (gt < 2 * KSZ * HSZ + 4096) { // blocks 128..143: 1/j table
            int idx = gt - 2 * KSZ * HSZ;
            g_inv[idx] = (idx > 0) ? (1.0f / (float)idx) : 0.0f;
        }
        // pair meta: block bid -> pairs bid, bid+256
        if (warp < 2 && lane == 0) {
            int p = (int)blockIdx.x + warp * GRID;
            if (p < NPAIR) {
                int ii, jj; pair_ij(p, ii, jj);
                double si = 0.0, sj = 0.0;
#pragma unroll 8
                for (int q = 0; q < NBB; q++) { si += g_pcnt[q][ii]; sj += g_pcnt[q][jj]; }
                float ci = (float)rint(si), cj = (float)rint(sj);
                float d2 = (ci + cj) - 2.0f;
                if (d2 == 0.0f) d2 += 1e-5f;
                double bd = 0.5 * (double)d2;
                PairMeta mt;
                mt.ci = ci; mt.cj = cj;
                mt.bf = (float)bd;
                mt.thresh = 1.5f / ((float)bd + 2.5f);
                mt.bd = bd;
                bool isint = (d2 == rintf(d2)) && (d2 >= 1.0f) && (d2 <= 4094.0f);
                mt.nu = isint ? (int)d2 : 0;
                mt.odd = ((int)d2) & 1;
                mt.lbeta = isint ? 0.0 : lbeta_half(bd);   // only fallback needs it
                g_meta[p] = mt;
            }
        }
        if (blockIdx.x == GRID - 1 && tid == TPB - 1) {
            g_acc = 0ULL;
            g_done = 0u;
        }
    }

    grid_barrier();

    // ================= Phase 3: pairs (x, top-20, betainc) + final =========
    {
        const int npair_here = ((int)blockIdx.x + GRID < NPAIR) ? 2 : 1;

        for (int q = 0; q < npair_here; q++) {
            int p = (int)blockIdx.x + q * GRID;
            int ii, jj; pair_ij(p, ii, jj);
            float ci = g_meta[p].ci, cj = g_meta[p].cj;
#pragma unroll
            for (int half = 0; half < 2; half++) {
                int h = tid + half * 256;
                float mi = g_m[ii][h], mj = g_m[jj][h];
                float wi = g_w[ii][h], wj = g_w[jj][h];
                float gmv = 0.5f * (mi + mj);
                float di = mi - gmv, dj = mj - gmv;
                float between = di * di * ci + dj * dj * cj;
                float x = between / (between + wi + wj);
                x = fminf(fmaxf(x, 1e-37f), 1.0f - 1e-5f);
                float v = x;
#pragma unroll
                for (int kk = 2; kk <= 32; kk <<= 1)
#pragma unroll
                    for (int jjs = kk >> 1; jjs > 0; jjs >>= 1) {
                        float o = __shfl_xor_sync(0xffffffffu, v, jjs);
                        bool up = ((lane & kk) == 0);
                        bool lo = ((lane & jjs) == 0);
                        v = (up == lo) ? fmaxf(v, o) : fminf(v, o);
                    }
                if (lane < 20) sm.s3.sx[q][warp * 40 + half * 20 + lane] = v;
            }
        }
        __syncthreads();

        if (warp < npair_here) {
            int p = (int)blockIdx.x + warp * GRID;
            PairMeta mt = g_meta[p];

            float r[10];
#pragma unroll
            for (int q = 0; q < 10; q++) r[q] = sm.s3.sx[warp][lane * 10 + q];
#pragma unroll
            for (int a = 0; a < 10; a++)
#pragma unroll
                for (int bq = 0; bq < 9 - a; bq++) {
                    float x0 = r[bq], x1 = r[bq + 1];
                    r[bq] = fmaxf(x0, x1); r[bq + 1] = fminf(x0, x1);
                }
            int ptr = 0;
            float head = r[0];
            float myx = 0.5f;   // dummy for lanes >= 20
#pragma unroll 1
            for (int t = 0; t < DSZ; t++) {
                float mx = head;
#pragma unroll
                for (int off = 16; off; off >>= 1)
                    mx = fmaxf(mx, __shfl_xor_sync(0xffffffffu, mx, off));
                int wl = (head == mx) ? lane : 32;
#pragma unroll
                for (int off = 16; off; off >>= 1)
                    wl = min(wl, __shfl_xor_sync(0xffffffffu, wl, off));
                if (lane == wl) {
                    ptr++;
                    float nh = -1e38f;
#pragma unroll
                    for (int q = 1; q < 10; q++) nh = (ptr == q) ? r[q] : nh;
                    head = nh;
                }
                if (lane == t) myx = mx;
            }

            // ---- I_x(1/2, nu/2) = Student-t A(t|nu): exact finite series ----
            double logI;
            float xx = myx;
            float uu = 1.0f - xx;
            if (mt.nu > 0) {
                if (mt.odd) {
                    int n = (mt.nu - 1) >> 1;
                    float D = 0.0f;
                    if (n > 0) {
                        float term = 1.0f; D = 1.0f;
#pragma unroll 1
                        for (int j = 1; j < n; j++) {
                            float f = 1.0f - g_inv[2 * j + 1];   // (2j)/(2j+1)
                            term *= uu * f;
                            D += term;
                        }
                    }
                    float s = sqrtf(xx), su = sqrtf(uu);
                    float A = 0.63661977236758134f * (asinf(s) + s * su * D);
                    logI = (double)logf(fminf(A, 1.0f));
                } else {
                    int n = mt.nu >> 1;
                    float term = 1.0f, S = 1.0f;
#pragma unroll 1
                    for (int j = 1; j < n; j++) {
                        float f = fmaf(-0.5f, g_inv[j], 1.0f);   // (2j-1)/(2j)
                        term *= uu * f;
                        S += term;
                    }
                    logI = (double)logf(fminf(sqrtf(xx) * S, 1.0f));
                }
            } else {
                // fallback CF (non-integer nu, e.g. d2==0 nudge)
                bool sel = xx < mt.thresh;
                float pa = sel ? 0.5f : mt.bf;
                float pb = sel ? mt.bf : 0.5f;
                float px = sel ? xx : uu;
                float cf = betacf_warp(pa, pb, px);
                double lbt = 0.5 * (double)logf(xx) + mt.bd * (double)log1pf(-xx) - mt.lbeta;
                if (sel) {
                    logI = lbt + (double)logf(2.0f * cf);
                } else {
                    double T = exp(lbt + (double)logf(cf / mt.bf));
                    logI = (double)log1pf(-(float)T);
                }
            }

            double contrib = (lane < DSZ) ? logI : 0.0;
#pragma unroll
            for (int off = 16; off; off >>= 1)
                contrib += __shfl_xor_sync(0xffffffffu, contrib, off);

            if (lane == 0) {
                long long fx = __double2ll_rn(contrib * 4294967296.0);
                atomicAdd(&g_acc, (unsigned long long)fx);
                __threadfence();
                unsigned int t = atomicAdd(&g_done, 1u);
                if (t == NPAIR - 1) {
                    long long total = (long long)atomicAdd(&g_acc, 0ULL);
                    out[0] = (float)(-(double)total * (1.0 / 4294967296.0));
                }
            }
        }
    }
}

extern "C" void kernel_launch(void* const* d_in, const int* in_sizes, int n_in,
                              void* d_out, int out_size) {
    (void)in_sizes; (void)n_in; (void)out_size;
    const float* hidden  = (const float*)d_in[0];
    const float* cluster = (const float*)d_in[1];
    float* out = (float*)d_out;
    fused_kernel<<<GRID, TPB>>>(hidden, cluster, out);
}